// round 10
// baseline (speedup 1.0000x reference)
#include <cuda_runtime.h>
#include <cuda_fp16.h>
#include <cstdint>

// NerfRenderer: N rays x S samples volume rendering. Single fused kernel.
// Outputs (concatenated in d_out, fp32):
//   image[N,3] | invdepth[N] | weights[N,S] | z_vals_log[N,S]
//
// R6 body (85.0% DRAM best measured): 128-thread blocks, one warp per ray,
// 4 samples/lane, float4 traffic, smem tables, warp-shuffle scan, prefetch.
// Delta vs R6: z_vals_log rows written via cp.async.bulk (shared->global,
// one 2304B bulk copy per warp) instead of per-lane STG in the hot loop.

#define WARPS_PER_BLOCK 4
#define BLOCK_THREADS (WARPS_PER_BLOCK * 32)
#define INNER_STEPS 384

__device__ __forceinline__ void warp_scan_prod(float P, int lane, float& excl, float& total)
{
    float incl = P;
    #pragma unroll
    for (int off = 1; off < 32; off <<= 1) {
        float v = __shfl_up_sync(0xffffffffu, incl, off);
        if (lane >= off) incl *= v;
    }
    excl = __shfl_up_sync(0xffffffffu, incl, 1);
    if (lane == 0) excl = 1.0f;
    total = __shfl_sync(0xffffffffu, incl, 31);
}

__device__ __forceinline__ unsigned int smem_u32(const void* p)
{
    unsigned int a;
    asm("{ .reg .u64 t; cvta.to.shared.u64 t, %1; cvt.u32.u64 %0, t; }"
        : "=r"(a) : "l"(p));
    return a;
}

template <int S_CT>
__global__ void __launch_bounds__(BLOCK_THREADS)
nerf_render_kernel(const float* __restrict__ sigmas,
                   const float* __restrict__ rgbs,
                   const float* __restrict__ bg,
                   float* __restrict__ out_img,
                   float* __restrict__ out_invd,
                   float* __restrict__ out_w,
                   float* __restrict__ out_zl,
                   int N, int S_rt)
{
    const int S = (S_CT > 0) ? S_CT : S_rt;

    extern __shared__ float smem[];
    float* s_zlog  = smem;             // [S] (16B-aligned: smem base)
    float* s_delta = smem + S;         // [S]
    float* s_rz    = smem + 2 * S;     // [S]
    float* s_z     = smem + 3 * S;     // [S] scratch (fp16-quantized z)

    const int tid = threadIdx.x;

    // ---- ray-invariant tables (match reference linspace -> 10^x -> fp16) ----
    for (int s = tid; s < S; s += BLOCK_THREADS) {
        float zlog;
        if (s < INNER_STEPS) {
            const float start = (float)(-1.3010299956639813);
            const float stop  = (float)(-1.3010299956639813 / 384.0);
            const float step  = (stop - start) / 383.0f;
            zlog = fmaf((float)s, step, start);
        } else {
            const float stop = (float)(2.0 - 2.0 / 192.0);
            const float step = stop / 191.0f;
            zlog = (float)(s - INNER_STEPS) * step;
        }
        float z  = exp10f(zlog);
        float zq = __half2float(__float2half(z));
        s_zlog[s] = zlog;
        s_z[s]    = zq;
        s_rz[s]   = 1.0f / zq;
    }
    __syncthreads();
    for (int s = tid; s < S; s += BLOCK_THREADS)
        s_delta[s] = (s < S - 1) ? (s_z[s + 1] - s_z[s]) : 1e10f;
    // make generic-proxy smem writes visible to the async (bulk-copy) proxy
    asm volatile("fence.proxy.async.shared::cta;" ::: "memory");
    __syncthreads();

    const int warp = tid >> 5;
    const int lane = tid & 31;
    const int ray  = blockIdx.x * WARPS_PER_BLOCK + warp;
    if (ray >= N) return;

    float* __restrict__ zlo = out_zl + (size_t)ray * S;

    // one bulk copy per warp: smem zlog table -> this ray's zlog row
    bool issued = false;
    if (lane == 0) {
        const unsigned int src = smem_u32(s_zlog);
        asm volatile(
            "cp.async.bulk.global.shared::cta.bulk_group [%0], [%1], %2;"
            :: "l"(zlo), "r"(src), "r"(S * 4) : "memory");
        asm volatile("cp.async.bulk.commit_group;" ::: "memory");
        issued = true;
    }

    const float*  sig  = sigmas + (size_t)ray * S;
    const float4* sg4  = (const float4*)sig;
    const float*  rgb  = rgbs + (size_t)ray * S * 3;
    const float4* rgb4 = (const float4*)rgb;
    float* __restrict__ wout = out_w + (size_t)ray * S;

    float T = 1.0f;
    float i0 = 0.f, i1 = 0.f, i2 = 0.f, invd = 0.f, wsum = 0.f;

    const int nFull = S >> 7;   // 128-sample chunks

    float4 sg, r0, r1, r2;
    if (nFull > 0) {
        sg = __ldcs(&sg4[lane]);
        const float4* rp = rgb4 + 3 * lane;
        r0 = __ldcs(rp); r1 = __ldcs(rp + 1); r2 = __ldcs(rp + 2);
    }

    #pragma unroll
    for (int ci = 0; ci < nFull; ci++) {
        const int c  = ci << 7;
        const int s0 = c + 4 * lane;

        float4 csg = sg, cr0 = r0, cr1 = r1, cr2 = r2;

        // prefetch next chunk before the dependent scan chain
        if (ci + 1 < nFull) {
            const int cn = c + 128;
            sg = __ldcs(&sg4[(cn >> 2) + lane]);
            const float4* rp = rgb4 + 3 * (cn >> 2) + 3 * lane;
            r0 = __ldcs(rp); r1 = __ldcs(rp + 1); r2 = __ldcs(rp + 2);
        }

        const float4 dl = *(const float4*)&s_delta[s0];
        const float4 rz = *(const float4*)&s_rz[s0];

        // e = exp(-sigma*delta); alpha = 1-e; 1-alpha+eps = e+eps
        const float e0 = __expf(-csg.x * dl.x);
        const float e1 = __expf(-csg.y * dl.y);
        const float e2 = __expf(-csg.z * dl.z);
        const float e3 = __expf(-csg.w * dl.w);
        const float p0 = e0 + 1e-10f, p1 = e1 + 1e-10f;
        const float p2 = e2 + 1e-10f, p3 = e3 + 1e-10f;

        float excl, ctot;
        warp_scan_prod((p0 * p1) * (p2 * p3), lane, excl, ctot);

        float cum = T * excl;
        const float w0 = (1.0f - e0) * cum; cum *= p0;
        const float w1 = (1.0f - e1) * cum; cum *= p1;
        const float w2 = (1.0f - e2) * cum; cum *= p2;
        const float w3 = (1.0f - e3) * cum;

        // rgb mapping: w0:(r0.x,y,z) w1:(r0.w,r1.x,y) w2:(r1.z,w,r2.x) w3:(r2.y,z,w)
        i0 = fmaf(w0, cr0.x, fmaf(w1, cr0.w, fmaf(w2, cr1.z, fmaf(w3, cr2.y, i0))));
        i1 = fmaf(w0, cr0.y, fmaf(w1, cr1.x, fmaf(w2, cr1.w, fmaf(w3, cr2.z, i1))));
        i2 = fmaf(w0, cr0.z, fmaf(w1, cr1.y, fmaf(w2, cr2.x, fmaf(w3, cr2.w, i2))));
        invd = fmaf(w0, rz.x, fmaf(w1, rz.y, fmaf(w2, rz.z, fmaf(w3, rz.w, invd))));
        wsum += (w0 + w1) + (w2 + w3);

        __stcs((float4*)&wout[s0], make_float4(w0, w1, w2, w3));

        T *= ctot;
    }

    // tail: 64 samples at 2 per lane (S % 128 == 64)
    const int ct = nFull << 7;
    if (ct < S) {
        const int s0 = ct + 2 * lane;
        const float2 sgt = __ldcs((const float2*)&sig[s0]);
        const float2* rp2 = (const float2*)(rgb + 3 * s0);
        const float2 ra = __ldcs(rp2);        // r0 g0
        const float2 rb = __ldcs(rp2 + 1);    // b0 r1
        const float2 rc = __ldcs(rp2 + 2);    // g1 b1

        const float2 dl = *(const float2*)&s_delta[s0];
        const float2 rz = *(const float2*)&s_rz[s0];

        const float e0 = __expf(-sgt.x * dl.x);
        const float e1 = __expf(-sgt.y * dl.y);
        const float p0 = e0 + 1e-10f, p1 = e1 + 1e-10f;

        float excl, ctot;
        warp_scan_prod(p0 * p1, lane, excl, ctot);

        float cum = T * excl;
        const float w0 = (1.0f - e0) * cum; cum *= p0;
        const float w1 = (1.0f - e1) * cum;

        i0 = fmaf(w0, ra.x, fmaf(w1, rb.y, i0));
        i1 = fmaf(w0, ra.y, fmaf(w1, rc.x, i1));
        i2 = fmaf(w0, rb.x, fmaf(w1, rc.y, i2));
        invd = fmaf(w0, rz.x, fmaf(w1, rz.y, invd));
        wsum += w0 + w1;

        __stcs((float2*)&wout[s0], make_float2(w0, w1));
    }

    #pragma unroll
    for (int off = 16; off; off >>= 1) {
        i0   += __shfl_xor_sync(0xffffffffu, i0, off);
        i1   += __shfl_xor_sync(0xffffffffu, i1, off);
        i2   += __shfl_xor_sync(0xffffffffu, i2, off);
        invd += __shfl_xor_sync(0xffffffffu, invd, off);
        wsum += __shfl_xor_sync(0xffffffffu, wsum, off);
    }

    if (lane == 0) {
        const float rem = 1.0f - wsum;
        out_img[3 * (size_t)ray + 0] = fmaf(rem, bg[0], i0);
        out_img[3 * (size_t)ray + 1] = fmaf(rem, bg[1], i1);
        out_img[3 * (size_t)ray + 2] = fmaf(rem, bg[2], i2);
        out_invd[ray] = invd;
    }

    // bulk copy must complete before smem (its source) is released at exit
    if (issued) {
        asm volatile("cp.async.bulk.wait_group 0;" ::: "memory");
    }
}

extern "C" void kernel_launch(void* const* d_in, const int* in_sizes, int n_in,
                              void* d_out, int out_size)
{
    // inputs: rays_o [N,3], rays_d [N,3], bg_color [3], sigmas [N,S], rgbs [N,S,3]
    const float* sigmas = (const float*)d_in[3];
    const float* rgbs   = (const float*)d_in[4];
    const float* bg     = (const float*)d_in[2];

    const int N = in_sizes[0] / 3;
    const int S = in_sizes[3] / N;

    float* out = (float*)d_out;
    float* out_img  = out;
    float* out_invd = out + (size_t)3 * N;
    float* out_w    = out + (size_t)4 * N;
    float* out_zl   = out + (size_t)4 * N + (size_t)N * S;

    const int grid = (N + WARPS_PER_BLOCK - 1) / WARPS_PER_BLOCK;
    const size_t shmem = (size_t)4 * S * sizeof(float);

    if (S == 576) {
        nerf_render_kernel<576><<<grid, BLOCK_THREADS, shmem>>>(
            sigmas, rgbs, bg, out_img, out_invd, out_w, out_zl, N, S);
    } else {
        nerf_render_kernel<0><<<grid, BLOCK_THREADS, shmem>>>(
            sigmas, rgbs, bg, out_img, out_invd, out_w, out_zl, N, S);
    }
}

// round 11
// speedup vs baseline: 1.1396x; 1.1396x over previous
#include <cuda_runtime.h>
#include <cuda_fp16.h>

// NerfRenderer: N rays x S samples volume rendering. Single fused kernel.
// Outputs (concatenated in d_out, fp32):
//   image[N,3] | invdepth[N] | weights[N,S] | z_vals_log[N,S]
//
// Final form (best measured: 85.0% DRAM, 6.74 TB/s): 128-thread blocks,
// one warp per ray, 4 samples/lane (128-sample chunks), float4 traffic,
// smem zlog/delta/rz tables, warp-shuffle scan for the transmittance
// cumprod, single-chunk prefetch, V=2 tail.
//
// Bracketed axes (all regressed or neutral): CTA size 256/64, split kernels,
// formula-zlog, forced occupancy, reordered stores, depth-2 pipeline,
// cp.async.bulk zlog writes. Traffic is compulsory (906 MB); this structure
// sits at the mixed read/write HBM ceiling.

#define WARPS_PER_BLOCK 4
#define BLOCK_THREADS (WARPS_PER_BLOCK * 32)
#define INNER_STEPS 384

__device__ __forceinline__ void warp_scan_prod(float P, int lane, float& excl, float& total)
{
    float incl = P;
    #pragma unroll
    for (int off = 1; off < 32; off <<= 1) {
        float v = __shfl_up_sync(0xffffffffu, incl, off);
        if (lane >= off) incl *= v;
    }
    excl = __shfl_up_sync(0xffffffffu, incl, 1);
    if (lane == 0) excl = 1.0f;
    total = __shfl_sync(0xffffffffu, incl, 31);
}

template <int S_CT>
__global__ void __launch_bounds__(BLOCK_THREADS)
nerf_render_kernel(const float* __restrict__ sigmas,
                   const float* __restrict__ rgbs,
                   const float* __restrict__ bg,
                   float* __restrict__ out_img,
                   float* __restrict__ out_invd,
                   float* __restrict__ out_w,
                   float* __restrict__ out_zl,
                   int N, int S_rt)
{
    const int S = (S_CT > 0) ? S_CT : S_rt;

    extern __shared__ float smem[];
    float* s_zlog  = smem;             // [S]
    float* s_delta = smem + S;         // [S]
    float* s_rz    = smem + 2 * S;     // [S]
    float* s_z     = smem + 3 * S;     // [S] scratch (fp16-quantized z)

    const int tid = threadIdx.x;

    // ---- ray-invariant tables (match reference linspace -> 10^x -> fp16) ----
    for (int s = tid; s < S; s += BLOCK_THREADS) {
        float zlog;
        if (s < INNER_STEPS) {
            const float start = (float)(-1.3010299956639813);
            const float stop  = (float)(-1.3010299956639813 / 384.0);
            const float step  = (stop - start) / 383.0f;
            zlog = fmaf((float)s, step, start);
        } else {
            const float stop = (float)(2.0 - 2.0 / 192.0);
            const float step = stop / 191.0f;
            zlog = (float)(s - INNER_STEPS) * step;
        }
        float z  = exp10f(zlog);
        float zq = __half2float(__float2half(z));
        s_zlog[s] = zlog;
        s_z[s]    = zq;
        s_rz[s]   = 1.0f / zq;
    }
    __syncthreads();
    for (int s = tid; s < S; s += BLOCK_THREADS)
        s_delta[s] = (s < S - 1) ? (s_z[s + 1] - s_z[s]) : 1e10f;
    __syncthreads();

    const int warp = tid >> 5;
    const int lane = tid & 31;
    const int ray  = blockIdx.x * WARPS_PER_BLOCK + warp;
    if (ray >= N) return;

    const float*  sig  = sigmas + (size_t)ray * S;
    const float4* sg4  = (const float4*)sig;
    const float*  rgb  = rgbs + (size_t)ray * S * 3;
    const float4* rgb4 = (const float4*)rgb;
    float* __restrict__ wout = out_w  + (size_t)ray * S;
    float* __restrict__ zlo  = out_zl + (size_t)ray * S;

    float T = 1.0f;
    float i0 = 0.f, i1 = 0.f, i2 = 0.f, invd = 0.f, wsum = 0.f;

    const int nFull = S >> 7;   // 128-sample chunks

    float4 sg, r0, r1, r2;
    if (nFull > 0) {
        sg = __ldcs(&sg4[lane]);
        const float4* rp = rgb4 + 3 * lane;
        r0 = __ldcs(rp); r1 = __ldcs(rp + 1); r2 = __ldcs(rp + 2);
    }

    #pragma unroll
    for (int ci = 0; ci < nFull; ci++) {
        const int c  = ci << 7;
        const int s0 = c + 4 * lane;

        float4 csg = sg, cr0 = r0, cr1 = r1, cr2 = r2;

        // prefetch next chunk before the dependent scan chain
        if (ci + 1 < nFull) {
            const int cn = c + 128;
            sg = __ldcs(&sg4[(cn >> 2) + lane]);
            const float4* rp = rgb4 + 3 * (cn >> 2) + 3 * lane;
            r0 = __ldcs(rp); r1 = __ldcs(rp + 1); r2 = __ldcs(rp + 2);
        }

        const float4 dl = *(const float4*)&s_delta[s0];
        const float4 rz = *(const float4*)&s_rz[s0];
        const float4 zl = *(const float4*)&s_zlog[s0];

        // e = exp(-sigma*delta); alpha = 1-e; 1-alpha+eps = e+eps
        const float e0 = __expf(-csg.x * dl.x);
        const float e1 = __expf(-csg.y * dl.y);
        const float e2 = __expf(-csg.z * dl.z);
        const float e3 = __expf(-csg.w * dl.w);
        const float p0 = e0 + 1e-10f, p1 = e1 + 1e-10f;
        const float p2 = e2 + 1e-10f, p3 = e3 + 1e-10f;

        float excl, ctot;
        warp_scan_prod((p0 * p1) * (p2 * p3), lane, excl, ctot);

        float cum = T * excl;
        const float w0 = (1.0f - e0) * cum; cum *= p0;
        const float w1 = (1.0f - e1) * cum; cum *= p1;
        const float w2 = (1.0f - e2) * cum; cum *= p2;
        const float w3 = (1.0f - e3) * cum;

        // rgb mapping: w0:(r0.x,y,z) w1:(r0.w,r1.x,y) w2:(r1.z,w,r2.x) w3:(r2.y,z,w)
        i0 = fmaf(w0, cr0.x, fmaf(w1, cr0.w, fmaf(w2, cr1.z, fmaf(w3, cr2.y, i0))));
        i1 = fmaf(w0, cr0.y, fmaf(w1, cr1.x, fmaf(w2, cr1.w, fmaf(w3, cr2.z, i1))));
        i2 = fmaf(w0, cr0.z, fmaf(w1, cr1.y, fmaf(w2, cr2.x, fmaf(w3, cr2.w, i2))));
        invd = fmaf(w0, rz.x, fmaf(w1, rz.y, fmaf(w2, rz.z, fmaf(w3, rz.w, invd))));
        wsum += (w0 + w1) + (w2 + w3);

        __stcs((float4*)&wout[s0], make_float4(w0, w1, w2, w3));
        __stcs((float4*)&zlo[s0], zl);

        T *= ctot;
    }

    // tail: 64 samples at 2 per lane (S % 128 == 64)
    const int ct = nFull << 7;
    if (ct < S) {
        const int s0 = ct + 2 * lane;
        const float2 sgt = __ldcs((const float2*)&sig[s0]);
        const float2* rp2 = (const float2*)(rgb + 3 * s0);
        const float2 ra = __ldcs(rp2);        // r0 g0
        const float2 rb = __ldcs(rp2 + 1);    // b0 r1
        const float2 rc = __ldcs(rp2 + 2);    // g1 b1

        const float2 dl = *(const float2*)&s_delta[s0];
        const float2 rz = *(const float2*)&s_rz[s0];
        const float2 zl = *(const float2*)&s_zlog[s0];

        const float e0 = __expf(-sgt.x * dl.x);
        const float e1 = __expf(-sgt.y * dl.y);
        const float p0 = e0 + 1e-10f, p1 = e1 + 1e-10f;

        float excl, ctot;
        warp_scan_prod(p0 * p1, lane, excl, ctot);

        float cum = T * excl;
        const float w0 = (1.0f - e0) * cum; cum *= p0;
        const float w1 = (1.0f - e1) * cum;

        i0 = fmaf(w0, ra.x, fmaf(w1, rb.y, i0));
        i1 = fmaf(w0, ra.y, fmaf(w1, rc.x, i1));
        i2 = fmaf(w0, rb.x, fmaf(w1, rc.y, i2));
        invd = fmaf(w0, rz.x, fmaf(w1, rz.y, invd));
        wsum += w0 + w1;

        __stcs((float2*)&wout[s0], make_float2(w0, w1));
        __stcs((float2*)&zlo[s0], zl);
    }

    #pragma unroll
    for (int off = 16; off; off >>= 1) {
        i0   += __shfl_xor_sync(0xffffffffu, i0, off);
        i1   += __shfl_xor_sync(0xffffffffu, i1, off);
        i2   += __shfl_xor_sync(0xffffffffu, i2, off);
        invd += __shfl_xor_sync(0xffffffffu, invd, off);
        wsum += __shfl_xor_sync(0xffffffffu, wsum, off);
    }

    if (lane == 0) {
        const float rem = 1.0f - wsum;
        out_img[3 * (size_t)ray + 0] = fmaf(rem, bg[0], i0);
        out_img[3 * (size_t)ray + 1] = fmaf(rem, bg[1], i1);
        out_img[3 * (size_t)ray + 2] = fmaf(rem, bg[2], i2);
        out_invd[ray] = invd;
    }
}

extern "C" void kernel_launch(void* const* d_in, const int* in_sizes, int n_in,
                              void* d_out, int out_size)
{
    // inputs: rays_o [N,3], rays_d [N,3], bg_color [3], sigmas [N,S], rgbs [N,S,3]
    const float* sigmas = (const float*)d_in[3];
    const float* rgbs   = (const float*)d_in[4];
    const float* bg     = (const float*)d_in[2];

    const int N = in_sizes[0] / 3;
    const int S = in_sizes[3] / N;

    float* out = (float*)d_out;
    float* out_img  = out;
    float* out_invd = out + (size_t)3 * N;
    float* out_w    = out + (size_t)4 * N;
    float* out_zl   = out + (size_t)4 * N + (size_t)N * S;

    const int grid = (N + WARPS_PER_BLOCK - 1) / WARPS_PER_BLOCK;
    const size_t shmem = (size_t)4 * S * sizeof(float);

    if (S == 576) {
        nerf_render_kernel<576><<<grid, BLOCK_THREADS, shmem>>>(
            sigmas, rgbs, bg, out_img, out_invd, out_w, out_zl, N, S);
    } else {
        nerf_render_kernel<0><<<grid, BLOCK_THREADS, shmem>>>(
            sigmas, rgbs, bg, out_img, out_invd, out_w, out_zl, N, S);
    }
}